// round 16
// baseline (speedup 1.0000x reference)
#include <cuda_runtime.h>
#include <cuda_bf16.h>
#include <math.h>

#define NN  50000
#define EE  800000
#define INC 512
#define HH  64
#define OC  40
#define NL  64
#define NBLK ((NN + 1023) / 1024)   // 49 scan blocks
#define CSTRIDE (391 * 256)         // lin1 grid stride for edge counting
#define LGRID ((NN / 4 + 7) / 8)    // 1563 blocks: one 4-node bundle per warp

// ---------------- device scratch (all zero-init; replay-invariant) ----------------
__device__ float g_dinv[NN];
__device__ int   g_cnt[NN];          // zeroed by k_scan after use
__device__ int   g_rowptr[NN + 1];
__device__ int   g_bsumbuf[2][NBLK]; // lookback aggregates, parity-buffered
__device__ int   g_done;
__device__ int   g_par;
__device__ int   g_fill[NN];
__device__ int2  g_edge[EE];         // (col, val-bits)
__device__ float g_x0[NN * HH];
__device__ float g_hbuf[2][NN * HH];
__device__ int   g_is64;

// ---------------- launch 0: lin1 + edge degree count + dtype detect ----------------
__global__ __launch_bounds__(256) void k_lin1(const float* __restrict__ x,
                                              const float* __restrict__ w1,
                                              const float* __restrict__ b1,
                                              const void* __restrict__ eiv) {
    {
        const int* ei32 = (const int*)eiv;
        bool is64 = (ei32[1] == 0) & (ei32[3] == 0) & (ei32[5] == 0) & (ei32[7] == 0);
        int gtid = blockIdx.x * 256 + threadIdx.x;
        if (gtid == 0) g_is64 = is64 ? 1 : 0;
        if (is64) {
            const long long* ei = (const long long*)eiv;
            for (int e = gtid; e < EE; e += CSTRIDE)
                atomicAdd(&g_cnt[(int)ei[EE + e]], 1);
        } else {
            for (int e = gtid; e < EE; e += CSTRIDE)
                atomicAdd(&g_cnt[ei32[EE + e]], 1);
        }
    }

    __shared__ float xsT[32][129];
    __shared__ float ws[32 * 64];
    int t = threadIdx.x;
    int half = t >> 7;
    int nl = t & 127;
    int node0 = blockIdx.x * 128;

    float acc[32];
#pragma unroll
    for (int c = 0; c < 32; c++) acc[c] = 0.f;

    for (int kt = 0; kt < INC; kt += 32) {
        for (int i = t; i < 32 * 64; i += 256)
            ws[i] = w1[(kt + (i >> 6)) * 64 + (i & 63)];
        for (int i = t; i < 1024; i += 256) {
            int r = i >> 3, c4 = i & 7;
            int node = node0 + r;
            float4 v = make_float4(0.f, 0.f, 0.f, 0.f);
            if (node < NN)
                v = *(const float4*)&x[(size_t)node * INC + kt + c4 * 4];
            xsT[c4 * 4 + 0][r] = v.x;
            xsT[c4 * 4 + 1][r] = v.y;
            xsT[c4 * 4 + 2][r] = v.z;
            xsT[c4 * 4 + 3][r] = v.w;
        }
        __syncthreads();
#pragma unroll 4
        for (int k = 0; k < 32; k++) {
            float xv = xsT[k][nl];
            const float4* wr = (const float4*)&ws[k * 64 + half * 32];
#pragma unroll
            for (int c4 = 0; c4 < 8; c4++) {
                float4 w4 = wr[c4];
                acc[c4 * 4 + 0] += xv * w4.x;
                acc[c4 * 4 + 1] += xv * w4.y;
                acc[c4 * 4 + 2] += xv * w4.z;
                acc[c4 * 4 + 3] += xv * w4.w;
            }
        }
        __syncthreads();
    }
    int node = node0 + nl;
    if (node < NN) {
        float* px = &g_x0[node * 64 + half * 32];
        float* ph = &g_hbuf[0][node * 64 + half * 32];
#pragma unroll
        for (int c4 = 0; c4 < 8; c4++) {
            float4 v;
            v.x = fmaxf(acc[c4 * 4 + 0] + b1[half * 32 + c4 * 4 + 0], 0.f);
            v.y = fmaxf(acc[c4 * 4 + 1] + b1[half * 32 + c4 * 4 + 1], 0.f);
            v.z = fmaxf(acc[c4 * 4 + 2] + b1[half * 32 + c4 * 4 + 2], 0.f);
            v.w = fmaxf(acc[c4 * 4 + 3] + b1[half * 32 + c4 * 4 + 3], 0.f);
            *(float4*)&px[c4 * 4] = v;
            *(float4*)&ph[c4 * 4] = v;
        }
    }
}

// ---------------- launch 1: single-pass lookback scan (replay-safe) ----------------
__global__ __launch_bounds__(1024) void k_scan() {
    __shared__ int wsum[32];
    __shared__ int pred[64];
    int par = g_par;
    int t = threadIdx.x, b = blockIdx.x;
    int i = b * 1024 + t;
    int v = (i < NN) ? g_cnt[i] : 0;
    int lane = t & 31, wid = t >> 5;
    int s = v;
#pragma unroll
    for (int o = 1; o < 32; o <<= 1) {
        int u = __shfl_up_sync(0xffffffffu, s, o);
        if (lane >= o) s += u;
    }
    if (lane == 31) wsum[wid] = s;
    __syncthreads();
    if (wid == 0) {
        int ws = wsum[lane];
#pragma unroll
        for (int o = 1; o < 32; o <<= 1) {
            int u = __shfl_up_sync(0xffffffffu, ws, o);
            if (lane >= o) ws += u;
        }
        wsum[lane] = ws;
    }
    __syncthreads();
    int excl = s - v + (wid > 0 ? wsum[wid - 1] : 0);
    if (t == 1023)
        atomicExch(&g_bsumbuf[par][b], (excl + v) | (1 << 30));
    if (t < 64) {
        int pv = 0;
        if (t < b) {
            while ((pv = atomicAdd(&g_bsumbuf[par][t], 0)) == 0) {}
            pv &= ~(1 << 30);
        }
        pred[t] = pv;
    }
    __syncthreads();
    for (int o = 32; o > 0; o >>= 1) {
        if (t < o) pred[t] += pred[t + o];
        __syncthreads();
    }
    int off = pred[0];
    if (i < NN) {
        g_rowptr[i] = excl + off;
        g_dinv[i] = rsqrtf((float)(v + 1));
        g_fill[i] = 0;
        g_cnt[i] = 0;
    }
    if (i == NN - 1) g_rowptr[NN] = EE;
    __syncthreads();
    __threadfence();
    if (t == 0) {
        int d = atomicAdd(&g_done, 1);
        if (d == NBLK - 1) {
            for (int j = 0; j < NBLK; j++) g_bsumbuf[par][j] = 0;
            g_done = 0;
            __threadfence();
            g_par = par ^ 1;
        }
    }
}

// ---------------- launch 2: fill CSR ----------------
__global__ void k_fill(const void* eiv) {
    int e = blockIdx.x * blockDim.x + threadIdx.x;
    if (e >= EE) return;
    int s, d;
    if (g_is64) {
        const long long* ei = (const long long*)eiv;
        s = (int)ei[e];
        d = (int)ei[EE + e];
    } else {
        const int* ei = (const int*)eiv;
        s = ei[e];
        d = ei[EE + e];
    }
    int pos = g_rowptr[d] + atomicAdd(&g_fill[d], 1);
    g_edge[pos] = make_int2(s, __float_as_int(g_dinv[s] * g_dinv[d]));
}

// one batch of 8 edges (zero-padded lanes contribute 0)
__device__ __forceinline__ void batch8(float4& acc, int cc, float vv, int j,
                                       const float4* __restrict__ hin4,
                                       int hl, int fl) {
    int sA = __shfl_sync(0xffffffffu, cc, j + hl);
    int sB = __shfl_sync(0xffffffffu, cc, j + 2 + hl);
    int sC = __shfl_sync(0xffffffffu, cc, j + 4 + hl);
    int sD = __shfl_sync(0xffffffffu, cc, j + 6 + hl);
    float vA = __shfl_sync(0xffffffffu, vv, j + hl);
    float vB = __shfl_sync(0xffffffffu, vv, j + 2 + hl);
    float vC = __shfl_sync(0xffffffffu, vv, j + 4 + hl);
    float vD = __shfl_sync(0xffffffffu, vv, j + 6 + hl);
    float4 hA = hin4[sA * 16 + fl];
    float4 hB = hin4[sB * 16 + fl];
    float4 hC = hin4[sC * 16 + fl];
    float4 hD = hin4[sD * 16 + fl];
    acc.x += vA * hA.x; acc.y += vA * hA.y;
    acc.z += vA * hA.z; acc.w += vA * hA.w;
    acc.x += vB * hB.x; acc.y += vB * hB.y;
    acc.z += vB * hB.z; acc.w += vB * hB.w;
    acc.x += vC * hC.x; acc.y += vC * hC.y;
    acc.z += vC * hC.z; acc.w += vC * hC.w;
    acc.x += vD * hD.x; acc.y += vD * hD.y;
    acc.z += vD * hD.z; acc.w += vD * hD.w;
}

// finalize one node: cross-half reduce + residual + stage z to smem
__device__ __forceinline__ void finalize_node(float4 acc, int node, int w, int q,
                                              const float4* __restrict__ hin4,
                                              const float4* __restrict__ x04,
                                              float (*zrow)[4][64],
                                              int hl, int fl) {
    acc.x += __shfl_xor_sync(0xffffffffu, acc.x, 16);
    acc.y += __shfl_xor_sync(0xffffffffu, acc.y, 16);
    acc.z += __shfl_xor_sync(0xffffffffu, acc.z, 16);
    acc.w += __shfl_xor_sync(0xffffffffu, acc.w, 16);
    if (hl == 0) {
        float di = g_dinv[node];
        float dd = di * di;
        float4 hme = hin4[node * 16 + fl];
        float4 xm = x04[node * 16 + fl];
        float4 z;
        z.x = 0.5f * (acc.x + dd * hme.x) + 0.5f * xm.x;
        z.y = 0.5f * (acc.y + dd * hme.y) + 0.5f * xm.y;
        z.z = 0.5f * (acc.z + dd * hme.z) + 0.5f * xm.z;
        z.w = 0.5f * (acc.w + dd * hme.w) + 0.5f * xm.w;
        *(float4*)&zrow[w][q][fl * 4] = z;   // STS.128, conflict-free
    }
}

// ---------------- launch 3+: fused GCNII layer ----------------
// 1563 blocks, EXACTLY one 4-node bundle per warp (no loop): HW block
// streaming balances work; body = R14 2-way pair-interleaved gather.
__global__ __launch_bounds__(256, 4) void k_layer(const float* __restrict__ W,
                                                  float beta, int p) {
    __shared__ float ws[64 * 64];
    __shared__ float zrow[8][4][64];    // [warp][node][k]
    int t = threadIdx.x, w = t >> 5, lane = t & 31;
    int l2 = lane * 2;
    int hl = lane >> 4;          // edge parity within pair
    int fl = lane & 15;          // feature quad id
    {   // vectorized W load: 1024 float4, 4 per thread
        const float4* W4 = (const float4*)W;
        float4* ws4 = (float4*)ws;
        for (int i = t; i < 1024; i += 256) ws4[i] = W4[i];
    }
    __syncthreads();

    int base = (blockIdx.x * 8 + w) * 4;
    if (base >= NN) return;      // safe: no block-wide sync after this

    const float4* __restrict__ hin4 = (const float4*)g_hbuf[p];
    const float4* __restrict__ x04 = (const float4*)g_x0;
    float* __restrict__ hout = g_hbuf[p ^ 1];
    float ob = 1.f - beta;

    // one rowptr load per bundle
    int rp = 0;
    if (lane < 5) rp = g_rowptr[base + lane];
    // prefetch all 4 nodes' first chunks (independent LDGs in flight)
    int2 Epre[4];
#pragma unroll
    for (int q = 0; q < 4; q++) {
        int a = __shfl_sync(0xffffffffu, rp, q);
        int b = __shfl_sync(0xffffffffu, rp, q + 1);
        Epre[q] = (a + lane < b) ? g_edge[a + lane] : make_int2(0, 0);
    }

#pragma unroll
    for (int pr = 0; pr < 2; pr++) {
        int qa = pr * 2, qb = qa + 1;
        int e0a = __shfl_sync(0xffffffffu, rp, qa);
        int e1a = __shfl_sync(0xffffffffu, rp, qa + 1);
        int e1b = __shfl_sync(0xffffffffu, rp, qb + 1);
        int cna = min(32, e1a - e0a);
        int cnb = min(32, e1b - e1a);
        int cmax = max(cna, cnb);
        float4 acca = make_float4(0.f, 0.f, 0.f, 0.f);
        float4 accb = make_float4(0.f, 0.f, 0.f, 0.f);
        int ca = Epre[qa].x; float va = __int_as_float(Epre[qa].y);
        int cb = Epre[qb].x; float vb = __int_as_float(Epre[qb].y);
        // interleaved first chunks: 2 independent chains in flight
        for (int j = 0; j < cmax; j += 8) {
            if (j < cna) batch8(acca, ca, va, j, hin4, hl, fl);
            if (j < cnb) batch8(accb, cb, vb, j, hin4, hl, fl);
        }
        // rare: degree > 32 (~3% of nodes), per-node spill chunks
        for (int eb = e0a + 32; eb < e1a; eb += 32) {
            int ee = eb + lane;
            int2 E = (ee < e1a) ? g_edge[ee] : make_int2(0, 0);
            int cn = min(32, e1a - eb);
            for (int j = 0; j < cn; j += 8)
                batch8(acca, E.x, __int_as_float(E.y), j, hin4, hl, fl);
        }
        for (int eb = e1a + 32; eb < e1b; eb += 32) {
            int ee = eb + lane;
            int2 E = (ee < e1b) ? g_edge[ee] : make_int2(0, 0);
            int cn = min(32, e1b - eb);
            for (int j = 0; j < cn; j += 8)
                batch8(accb, E.x, __int_as_float(E.y), j, hin4, hl, fl);
        }
        finalize_node(acca, base + qa, w, qa, hin4, x04, zrow, hl, fl);
        finalize_node(accb, base + qb, w, qb, hin4, x04, zrow, hl, fl);
    }
    __syncwarp();

    // GEMM: per k-quad, 4 broadcast LDS.128 (one per node) + 4 LDS.64 (W)
    float2 sA = make_float2(0.f, 0.f), sB = make_float2(0.f, 0.f);
    float2 sC = make_float2(0.f, 0.f), sD = make_float2(0.f, 0.f);
#pragma unroll
    for (int k4 = 0; k4 < 16; k4++) {
        float4 zA = *(const float4*)&zrow[w][0][k4 * 4];
        float4 zB = *(const float4*)&zrow[w][1][k4 * 4];
        float4 zC = *(const float4*)&zrow[w][2][k4 * 4];
        float4 zD = *(const float4*)&zrow[w][3][k4 * 4];
#pragma unroll
        for (int j = 0; j < 4; j++) {
            float2 wk = *(const float2*)&ws[(k4 * 4 + j) * 64 + l2];
            float za = (j == 0) ? zA.x : (j == 1) ? zA.y : (j == 2) ? zA.z : zA.w;
            float zb = (j == 0) ? zB.x : (j == 1) ? zB.y : (j == 2) ? zB.z : zB.w;
            float zc = (j == 0) ? zC.x : (j == 1) ? zC.y : (j == 2) ? zC.z : zC.w;
            float zd = (j == 0) ? zD.x : (j == 1) ? zD.y : (j == 2) ? zD.z : zD.w;
            sA.x += za * wk.x; sA.y += za * wk.y;
            sB.x += zb * wk.x; sB.y += zb * wk.y;
            sC.x += zc * wk.x; sC.y += zc * wk.y;
            sD.x += zd * wk.x; sD.y += zd * wk.y;
        }
    }
#pragma unroll
    for (int q = 0; q < 4; q++) {
        int node = base + q;
        float2 zc2 = *(const float2*)&zrow[w][q][l2];
        float2 sq = (q == 0) ? sA : (q == 1) ? sB : (q == 2) ? sC : sD;
        float o0 = fmaxf(ob * zc2.x + beta * sq.x, 0.f);
        float o1 = fmaxf(ob * zc2.y + beta * sq.y, 0.f);
        *(float2*)&hout[node * 64 + l2] = make_float2(o0, o1);
    }
}

// ---------------- output: lin2 + log_softmax ----------------
__global__ __launch_bounds__(256) void k_out(const float* __restrict__ w2,
                                             const float* __restrict__ b2,
                                             float* __restrict__ out) {
    __shared__ float ws[64 * OC];
    __shared__ float bs[OC];
    __shared__ float zsm[8][64];
    int t = threadIdx.x, w = t >> 5, lane = t & 31;
    for (int i = t; i < 64 * OC; i += 256) ws[i] = w2[i];
    if (t < OC) bs[t] = b2[t];
    __syncthreads();

    const float* h = g_hbuf[0];  // NL even -> final state in buffer 0
    int warpG = blockIdx.x * 8 + w;
    int nW = gridDim.x * 8;

    for (int node = warpG; node < NN; node += nW) {
        float2 h2 = *(const float2*)&h[node * 64 + lane * 2];
        *(float2*)&zsm[w][lane * 2] = h2;
        __syncwarp();
        int c0 = lane;
        int c1 = lane + 32;
        float v0 = bs[c0];
        float v1 = (lane < 8) ? bs[c1] : 0.f;
#pragma unroll
        for (int k = 0; k < 64; k++) {
            float zk = zsm[w][k];
            v0 += zk * ws[k * OC + c0];
            if (lane < 8) v1 += zk * ws[k * OC + c1];
        }
        float m = v0;
        if (lane < 8) m = fmaxf(m, v1);
#pragma unroll
        for (int o = 16; o > 0; o >>= 1)
            m = fmaxf(m, __shfl_xor_sync(0xffffffffu, m, o));
        float se = expf(v0 - m) + ((lane < 8) ? expf(v1 - m) : 0.f);
#pragma unroll
        for (int o = 16; o > 0; o >>= 1)
            se += __shfl_xor_sync(0xffffffffu, se, o);
        float lse = m + logf(se);
        out[node * OC + c0] = v0 - lse;
        if (lane < 8) out[node * OC + c1] = v1 - lse;
        __syncwarp();
    }
}

// ---------------- launch ----------------
extern "C" void kernel_launch(void* const* d_in, const int* in_sizes, int n_in,
                              void* d_out, int out_size) {
    (void)in_sizes; (void)n_in; (void)out_size;
    const float* x  = (const float*)d_in[0];
    const void*  ei = d_in[1];
    const float* w1 = (const float*)d_in[2];
    const float* b1 = (const float*)d_in[3];
    const float* cw = (const float*)d_in[4];
    const float* w2 = (const float*)d_in[5];
    const float* b2 = (const float*)d_in[6];
    float* out = (float*)d_out;

    k_lin1<<<391, 256>>>(x, w1, b1, ei);        // #0
    k_scan<<<NBLK, 1024>>>();                    // #1
    k_fill<<<(EE + 255) / 256, 256>>>(ei);       // #2
    for (int l = 0; l < NL; l++) {               // #3 = layer 0 (profiled)
        float beta = logf(1.0f / (float)(l + 1) + 1.0f);
        k_layer<<<LGRID, 256>>>(cw + (size_t)l * HH * HH, beta, l & 1);
    }
    k_out<<<512, 256>>>(w2, b2, out);
}

// round 17
// speedup vs baseline: 1.5488x; 1.5488x over previous
#include <cuda_runtime.h>
#include <cuda_bf16.h>
#include <math.h>

#define NN  50000
#define EE  800000
#define INC 512
#define HH  64
#define OC  40
#define NL  64
#define NBLK ((NN + 1023) / 1024)   // 49 scan blocks
#define CSTRIDE (391 * 256)         // lin1 grid stride for edge counting

// ---------------- device scratch (all zero-init; replay-invariant) ----------------
__device__ float g_dinv[NN];
__device__ int   g_cnt[NN];          // zeroed by k_scan after use
__device__ int   g_rowptr[NN + 1];
__device__ int   g_bsumbuf[2][NBLK]; // lookback aggregates, parity-buffered
__device__ int   g_done;
__device__ int   g_par;
__device__ int   g_fill[NN];
__device__ int2  g_edge[EE];         // (col, val-bits)
__device__ float g_x0[NN * HH];
__device__ float g_hbuf[2][NN * HH];
__device__ int   g_is64;

// ---------------- launch 0: lin1 + edge degree count + dtype detect ----------------
__global__ __launch_bounds__(256) void k_lin1(const float* __restrict__ x,
                                              const float* __restrict__ w1,
                                              const float* __restrict__ b1,
                                              const void* __restrict__ eiv) {
    {
        const int* ei32 = (const int*)eiv;
        bool is64 = (ei32[1] == 0) & (ei32[3] == 0) & (ei32[5] == 0) & (ei32[7] == 0);
        int gtid = blockIdx.x * 256 + threadIdx.x;
        if (gtid == 0) g_is64 = is64 ? 1 : 0;
        if (is64) {
            const long long* ei = (const long long*)eiv;
            for (int e = gtid; e < EE; e += CSTRIDE)
                atomicAdd(&g_cnt[(int)ei[EE + e]], 1);
        } else {
            for (int e = gtid; e < EE; e += CSTRIDE)
                atomicAdd(&g_cnt[ei32[EE + e]], 1);
        }
    }

    __shared__ float xsT[32][129];
    __shared__ float ws[32 * 64];
    int t = threadIdx.x;
    int half = t >> 7;
    int nl = t & 127;
    int node0 = blockIdx.x * 128;

    float acc[32];
#pragma unroll
    for (int c = 0; c < 32; c++) acc[c] = 0.f;

    for (int kt = 0; kt < INC; kt += 32) {
        for (int i = t; i < 32 * 64; i += 256)
            ws[i] = w1[(kt + (i >> 6)) * 64 + (i & 63)];
        for (int i = t; i < 1024; i += 256) {
            int r = i >> 3, c4 = i & 7;
            int node = node0 + r;
            float4 v = make_float4(0.f, 0.f, 0.f, 0.f);
            if (node < NN)
                v = *(const float4*)&x[(size_t)node * INC + kt + c4 * 4];
            xsT[c4 * 4 + 0][r] = v.x;
            xsT[c4 * 4 + 1][r] = v.y;
            xsT[c4 * 4 + 2][r] = v.z;
            xsT[c4 * 4 + 3][r] = v.w;
        }
        __syncthreads();
#pragma unroll 4
        for (int k = 0; k < 32; k++) {
            float xv = xsT[k][nl];
            const float4* wr = (const float4*)&ws[k * 64 + half * 32];
#pragma unroll
            for (int c4 = 0; c4 < 8; c4++) {
                float4 w4 = wr[c4];
                acc[c4 * 4 + 0] += xv * w4.x;
                acc[c4 * 4 + 1] += xv * w4.y;
                acc[c4 * 4 + 2] += xv * w4.z;
                acc[c4 * 4 + 3] += xv * w4.w;
            }
        }
        __syncthreads();
    }
    int node = node0 + nl;
    if (node < NN) {
        float* px = &g_x0[node * 64 + half * 32];
        float* ph = &g_hbuf[0][node * 64 + half * 32];
#pragma unroll
        for (int c4 = 0; c4 < 8; c4++) {
            float4 v;
            v.x = fmaxf(acc[c4 * 4 + 0] + b1[half * 32 + c4 * 4 + 0], 0.f);
            v.y = fmaxf(acc[c4 * 4 + 1] + b1[half * 32 + c4 * 4 + 1], 0.f);
            v.z = fmaxf(acc[c4 * 4 + 2] + b1[half * 32 + c4 * 4 + 2], 0.f);
            v.w = fmaxf(acc[c4 * 4 + 3] + b1[half * 32 + c4 * 4 + 3], 0.f);
            *(float4*)&px[c4 * 4] = v;
            *(float4*)&ph[c4 * 4] = v;
        }
    }
}

// ---------------- launch 1: single-pass lookback scan (replay-safe) ----------------
__global__ __launch_bounds__(1024) void k_scan() {
    __shared__ int wsum[32];
    __shared__ int pred[64];
    int par = g_par;
    int t = threadIdx.x, b = blockIdx.x;
    int i = b * 1024 + t;
    int v = (i < NN) ? g_cnt[i] : 0;
    int lane = t & 31, wid = t >> 5;
    int s = v;
#pragma unroll
    for (int o = 1; o < 32; o <<= 1) {
        int u = __shfl_up_sync(0xffffffffu, s, o);
        if (lane >= o) s += u;
    }
    if (lane == 31) wsum[wid] = s;
    __syncthreads();
    if (wid == 0) {
        int ws = wsum[lane];
#pragma unroll
        for (int o = 1; o < 32; o <<= 1) {
            int u = __shfl_up_sync(0xffffffffu, ws, o);
            if (lane >= o) ws += u;
        }
        wsum[lane] = ws;
    }
    __syncthreads();
    int excl = s - v + (wid > 0 ? wsum[wid - 1] : 0);
    if (t == 1023)
        atomicExch(&g_bsumbuf[par][b], (excl + v) | (1 << 30));
    if (t < 64) {
        int pv = 0;
        if (t < b) {
            while ((pv = atomicAdd(&g_bsumbuf[par][t], 0)) == 0) {}
            pv &= ~(1 << 30);
        }
        pred[t] = pv;
    }
    __syncthreads();
    for (int o = 32; o > 0; o >>= 1) {
        if (t < o) pred[t] += pred[t + o];
        __syncthreads();
    }
    int off = pred[0];
    if (i < NN) {
        g_rowptr[i] = excl + off;
        g_dinv[i] = rsqrtf((float)(v + 1));
        g_fill[i] = 0;
        g_cnt[i] = 0;
    }
    if (i == NN - 1) g_rowptr[NN] = EE;
    __syncthreads();
    __threadfence();
    if (t == 0) {
        int d = atomicAdd(&g_done, 1);
        if (d == NBLK - 1) {
            for (int j = 0; j < NBLK; j++) g_bsumbuf[par][j] = 0;
            g_done = 0;
            __threadfence();
            g_par = par ^ 1;
        }
    }
}

// ---------------- launch 2: fill CSR ----------------
__global__ void k_fill(const void* eiv) {
    int e = blockIdx.x * blockDim.x + threadIdx.x;
    if (e >= EE) return;
    int s, d;
    if (g_is64) {
        const long long* ei = (const long long*)eiv;
        s = (int)ei[e];
        d = (int)ei[EE + e];
    } else {
        const int* ei = (const int*)eiv;
        s = ei[e];
        d = ei[EE + e];
    }
    int pos = g_rowptr[d] + atomicAdd(&g_fill[d], 1);
    g_edge[pos] = make_int2(s, __float_as_int(g_dinv[s] * g_dinv[d]));
}

// one batch of 8 edges (zero-padded lanes contribute 0)
__device__ __forceinline__ void batch8(float4& acc, int cc, float vv, int j,
                                       const float4* __restrict__ hin4,
                                       int hl, int fl) {
    int sA = __shfl_sync(0xffffffffu, cc, j + hl);
    int sB = __shfl_sync(0xffffffffu, cc, j + 2 + hl);
    int sC = __shfl_sync(0xffffffffu, cc, j + 4 + hl);
    int sD = __shfl_sync(0xffffffffu, cc, j + 6 + hl);
    float vA = __shfl_sync(0xffffffffu, vv, j + hl);
    float vB = __shfl_sync(0xffffffffu, vv, j + 2 + hl);
    float vC = __shfl_sync(0xffffffffu, vv, j + 4 + hl);
    float vD = __shfl_sync(0xffffffffu, vv, j + 6 + hl);
    float4 hA = hin4[sA * 16 + fl];
    float4 hB = hin4[sB * 16 + fl];
    float4 hC = hin4[sC * 16 + fl];
    float4 hD = hin4[sD * 16 + fl];
    acc.x += vA * hA.x; acc.y += vA * hA.y;
    acc.z += vA * hA.z; acc.w += vA * hA.w;
    acc.x += vB * hB.x; acc.y += vB * hB.y;
    acc.z += vB * hB.z; acc.w += vB * hB.w;
    acc.x += vC * hC.x; acc.y += vC * hC.y;
    acc.z += vC * hC.z; acc.w += vC * hC.w;
    acc.x += vD * hD.x; acc.y += vD * hD.y;
    acc.z += vD * hD.z; acc.w += vD * hD.w;
}

// finalize one node: cross-half reduce + residual + stage z to smem
__device__ __forceinline__ void finalize_node(float4 acc, int node, int w, int q,
                                              const float4* __restrict__ hin4,
                                              const float4* __restrict__ x04,
                                              float (*zrow)[4][64],
                                              int hl, int fl) {
    acc.x += __shfl_xor_sync(0xffffffffu, acc.x, 16);
    acc.y += __shfl_xor_sync(0xffffffffu, acc.y, 16);
    acc.z += __shfl_xor_sync(0xffffffffu, acc.z, 16);
    acc.w += __shfl_xor_sync(0xffffffffu, acc.w, 16);
    if (hl == 0) {
        float di = g_dinv[node];
        float dd = di * di;
        float4 hme = hin4[node * 16 + fl];
        float4 xm = x04[node * 16 + fl];
        float4 z;
        z.x = 0.5f * (acc.x + dd * hme.x) + 0.5f * xm.x;
        z.y = 0.5f * (acc.y + dd * hme.y) + 0.5f * xm.y;
        z.z = 0.5f * (acc.z + dd * hme.z) + 0.5f * xm.z;
        z.w = 0.5f * (acc.w + dd * hme.w) + 0.5f * xm.w;
        *(float4*)&zrow[w][q][fl * 4] = z;   // STS.128, conflict-free
    }
}

// streaming (evict-first) edge-record load: single-use data, keep L1 for h rows
__device__ __forceinline__ int2 ldcs_edge(const int2* p) {
    return __ldcs(p);
}

// ---------------- launch 3+: fused GCNII layer (R14 best + ldcs/f4-W) ----------------
// warp = 4 nodes, gathered as two INTERLEAVED pairs: nodes (2p, 2p+1) share
// one j-loop, alternating 8-edge batches -> 2x loads/FMA-chains in flight.
__global__ __launch_bounds__(256, 4) void k_layer(const float* __restrict__ W,
                                                  float beta, int p) {
    __shared__ float ws[64 * 64];
    __shared__ float zrow[8][4][64];    // [warp][node][k]
    int t = threadIdx.x, w = t >> 5, lane = t & 31;
    int l2 = lane * 2;
    int hl = lane >> 4;          // edge parity within pair
    int fl = lane & 15;          // feature quad id
    {   // vectorized W load: 1024 float4, 4 per thread
        const float4* W4 = (const float4*)W;
        float4* ws4 = (float4*)ws;
        for (int i = t; i < 1024; i += 256) ws4[i] = W4[i];
    }
    __syncthreads();

    const float4* __restrict__ hin4 = (const float4*)g_hbuf[p];
    const float4* __restrict__ x04 = (const float4*)g_x0;
    float* __restrict__ hout = g_hbuf[p ^ 1];
    int warpG = blockIdx.x * 8 + w;
    int nW = gridDim.x * 8;
    float ob = 1.f - beta;

    for (int base = warpG * 4; base < NN; base += nW * 4) {
        // one rowptr load per bundle
        int rp = 0;
        if (lane < 5) rp = g_rowptr[base + lane];
        // prefetch all 4 nodes' first chunks (independent LDGs in flight)
        int2 Epre[4];
#pragma unroll
        for (int q = 0; q < 4; q++) {
            int a = __shfl_sync(0xffffffffu, rp, q);
            int b = __shfl_sync(0xffffffffu, rp, q + 1);
            Epre[q] = (a + lane < b) ? ldcs_edge(&g_edge[a + lane]) : make_int2(0, 0);
        }

#pragma unroll
        for (int pr = 0; pr < 2; pr++) {
            int qa = pr * 2, qb = qa + 1;
            int e0a = __shfl_sync(0xffffffffu, rp, qa);
            int e1a = __shfl_sync(0xffffffffu, rp, qa + 1);
            int e1b = __shfl_sync(0xffffffffu, rp, qb + 1);
            int cna = min(32, e1a - e0a);
            int cnb = min(32, e1b - e1a);
            int cmax = max(cna, cnb);
            float4 acca = make_float4(0.f, 0.f, 0.f, 0.f);
            float4 accb = make_float4(0.f, 0.f, 0.f, 0.f);
            int ca = Epre[qa].x; float va = __int_as_float(Epre[qa].y);
            int cb = Epre[qb].x; float vb = __int_as_float(Epre[qb].y);
            // interleaved first chunks: 2 independent chains in flight
            for (int j = 0; j < cmax; j += 8) {
                if (j < cna) batch8(acca, ca, va, j, hin4, hl, fl);
                if (j < cnb) batch8(accb, cb, vb, j, hin4, hl, fl);
            }
            // rare: degree > 32 (~3% of nodes), per-node spill chunks
            for (int eb = e0a + 32; eb < e1a; eb += 32) {
                int ee = eb + lane;
                int2 E = (ee < e1a) ? ldcs_edge(&g_edge[ee]) : make_int2(0, 0);
                int cn = min(32, e1a - eb);
                for (int j = 0; j < cn; j += 8)
                    batch8(acca, E.x, __int_as_float(E.y), j, hin4, hl, fl);
            }
            for (int eb = e1a + 32; eb < e1b; eb += 32) {
                int ee = eb + lane;
                int2 E = (ee < e1b) ? ldcs_edge(&g_edge[ee]) : make_int2(0, 0);
                int cn = min(32, e1b - eb);
                for (int j = 0; j < cn; j += 8)
                    batch8(accb, E.x, __int_as_float(E.y), j, hin4, hl, fl);
            }
            finalize_node(acca, base + qa, w, qa, hin4, x04, zrow, hl, fl);
            finalize_node(accb, base + qb, w, qb, hin4, x04, zrow, hl, fl);
        }
        __syncwarp();

        // GEMM: per k-quad, 4 broadcast LDS.128 (one per node) + 4 LDS.64 (W)
        float2 sA = make_float2(0.f, 0.f), sB = make_float2(0.f, 0.f);
        float2 sC = make_float2(0.f, 0.f), sD = make_float2(0.f, 0.f);
#pragma unroll
        for (int k4 = 0; k4 < 16; k4++) {
            float4 zA = *(const float4*)&zrow[w][0][k4 * 4];
            float4 zB = *(const float4*)&zrow[w][1][k4 * 4];
            float4 zC = *(const float4*)&zrow[w][2][k4 * 4];
            float4 zD = *(const float4*)&zrow[w][3][k4 * 4];
#pragma unroll
            for (int j = 0; j < 4; j++) {
                float2 wk = *(const float2*)&ws[(k4 * 4 + j) * 64 + l2];
                float za = (j == 0) ? zA.x : (j == 1) ? zA.y : (j == 2) ? zA.z : zA.w;
                float zb = (j == 0) ? zB.x : (j == 1) ? zB.y : (j == 2) ? zB.z : zB.w;
                float zc = (j == 0) ? zC.x : (j == 1) ? zC.y : (j == 2) ? zC.z : zC.w;
                float zd = (j == 0) ? zD.x : (j == 1) ? zD.y : (j == 2) ? zD.z : zD.w;
                sA.x += za * wk.x; sA.y += za * wk.y;
                sB.x += zb * wk.x; sB.y += zb * wk.y;
                sC.x += zc * wk.x; sC.y += zc * wk.y;
                sD.x += zd * wk.x; sD.y += zd * wk.y;
            }
        }
#pragma unroll
        for (int q = 0; q < 4; q++) {
            int node = base + q;
            float2 zc2 = *(const float2*)&zrow[w][q][l2];
            float2 sq = (q == 0) ? sA : (q == 1) ? sB : (q == 2) ? sC : sD;
            float o0 = fmaxf(ob * zc2.x + beta * sq.x, 0.f);
            float o1 = fmaxf(ob * zc2.y + beta * sq.y, 0.f);
            *(float2*)&hout[node * 64 + l2] = make_float2(o0, o1);
        }
        __syncwarp();
    }
}

// ---------------- output: lin2 + log_softmax ----------------
__global__ __launch_bounds__(256) void k_out(const float* __restrict__ w2,
                                             const float* __restrict__ b2,
                                             float* __restrict__ out) {
    __shared__ float ws[64 * OC];
    __shared__ float bs[OC];
    __shared__ float zsm[8][64];
    int t = threadIdx.x, w = t >> 5, lane = t & 31;
    for (int i = t; i < 64 * OC; i += 256) ws[i] = w2[i];
    if (t < OC) bs[t] = b2[t];
    __syncthreads();

    const float* h = g_hbuf[0];  // NL even -> final state in buffer 0
    int warpG = blockIdx.x * 8 + w;
    int nW = gridDim.x * 8;

    for (int node = warpG; node < NN; node += nW) {
        float2 h2 = *(const float2*)&h[node * 64 + lane * 2];
        *(float2*)&zsm[w][lane * 2] = h2;
        __syncwarp();
        int c0 = lane;
        int c1 = lane + 32;
        float v0 = bs[c0];
        float v1 = (lane < 8) ? bs[c1] : 0.f;
#pragma unroll
        for (int k = 0; k < 64; k++) {
            float zk = zsm[w][k];
            v0 += zk * ws[k * OC + c0];
            if (lane < 8) v1 += zk * ws[k * OC + c1];
        }
        float m = v0;
        if (lane < 8) m = fmaxf(m, v1);
#pragma unroll
        for (int o = 16; o > 0; o >>= 1)
            m = fmaxf(m, __shfl_xor_sync(0xffffffffu, m, o));
        float se = expf(v0 - m) + ((lane < 8) ? expf(v1 - m) : 0.f);
#pragma unroll
        for (int o = 16; o > 0; o >>= 1)
            se += __shfl_xor_sync(0xffffffffu, se, o);
        float lse = m + logf(se);
        out[node * OC + c0] = v0 - lse;
        if (lane < 8) out[node * OC + c1] = v1 - lse;
        __syncwarp();
    }
}

// ---------------- launch ----------------
extern "C" void kernel_launch(void* const* d_in, const int* in_sizes, int n_in,
                              void* d_out, int out_size) {
    (void)in_sizes; (void)n_in; (void)out_size;
    const float* x  = (const float*)d_in[0];
    const void*  ei = d_in[1];
    const float* w1 = (const float*)d_in[2];
    const float* b1 = (const float*)d_in[3];
    const float* cw = (const float*)d_in[4];
    const float* w2 = (const float*)d_in[5];
    const float* b2 = (const float*)d_in[6];
    float* out = (float*)d_out;

    k_lin1<<<391, 256>>>(x, w1, b1, ei);        // #0
    k_scan<<<NBLK, 1024>>>();                    // #1
    k_fill<<<(EE + 255) / 256, 256>>>(ei);       // #2
    for (int l = 0; l < NL; l++) {               // #3 = layer 0 (profiled)
        float beta = logf(1.0f / (float)(l + 1) + 1.0f);
        k_layer<<<148 * 8, 256>>>(cw + (size_t)l * HH * HH, beta, l & 1);
    }
    k_out<<<512, 256>>>(w2, b2, out);
}